// round 1
// baseline (speedup 1.0000x reference)
#include <cuda_runtime.h>
#include <cstdint>

typedef unsigned long long u64;

#define DDIM 64
#define BBIG 64
#define BLOCK 352
#define BTILE 16
#define NPASS (BBIG / BTILE)

__device__ __forceinline__ u64 f32x2_add(u64 a, u64 b) {
    u64 r;
    asm("add.rn.f32x2 %0, %1, %2;" : "=l"(r) : "l"(a), "l"(b));
    return r;
}
// clear sign bits of both packed floats: |x| on a pair in one and.b64 (2 LOP3)
__device__ __forceinline__ u64 f32x2_abs(u64 a) {
    u64 r;
    asm("and.b64 %0, %1, 0x7FFFFFFF7FFFFFFF;" : "=l"(r) : "l"(a));
    return r;
}
__device__ __forceinline__ u64 pack2(float lo, float hi) {
    u64 r;
    asm("mov.b64 %0, {%1, %2};" : "=l"(r) : "f"(lo), "f"(hi));
    return r;
}

__global__ void __launch_bounds__(BLOCK) wl1_kernel(
    const float* __restrict__ q,
    const float* __restrict__ X,
    const float* __restrict__ fw,
    float* __restrict__ out,
    int N)
{
    __shared__ float w_s[DDIM];
    __shared__ float q_s[BBIG * DDIM];   // w-scaled q, [b][d] row-major, 16 KB

    const int tid = threadIdx.x;

    // 1) softplus(feature_weights), numerically-stable form matching jax
    if (tid < DDIM) {
        float f = fw[tid];
        w_s[tid] = fmaxf(f, 0.0f) + log1pf(expf(-fabsf(f)));
    }
    __syncthreads();

    // 2) stage w-scaled q into smem: q'[b][d] = w[d] * q[b][d]
    for (int i = tid; i < BBIG * DDIM; i += BLOCK) {
        q_s[i] = q[i] * w_s[i & (DDIM - 1)];
    }
    __syncthreads();

    const int n = blockIdx.x * BLOCK + tid;
    if (n >= N) return;   // no __syncthreads below this point

    // 3) load this thread's X row once, scale by w, negate, pack into f32x2 pairs
    u64 nx[DDIM / 2];
    const float4* xr = reinterpret_cast<const float4*>(X + (size_t)n * DDIM);
    #pragma unroll
    for (int j = 0; j < DDIM / 4; ++j) {
        float4 v = xr[j];
        float a = -(v.x * w_s[4 * j + 0]);
        float b = -(v.y * w_s[4 * j + 1]);
        float c = -(v.z * w_s[4 * j + 2]);
        float d = -(v.w * w_s[4 * j + 3]);
        nx[2 * j]     = pack2(a, b);
        nx[2 * j + 1] = pack2(c, d);
    }

    uint32_t qbase = (uint32_t)__cvta_generic_to_shared(q_s);

    // 4) mainloop: 4 passes over b-tiles of 16; d fully unrolled (nx stays in regs)
    for (int p = 0; p < NPASS; ++p) {
        u64 acc[BTILE];
        #pragma unroll
        for (int t = 0; t < BTILE; ++t) acc[t] = 0ull;   // {0.0f, 0.0f}

        const uint32_t pbase = qbase + (uint32_t)(p * BTILE * DDIM * 4);

        #pragma unroll
        for (int d4 = 0; d4 < DDIM / 4; ++d4) {
            #pragma unroll
            for (int t = 0; t < BTILE; ++t) {
                uint32_t addr = pbase + (uint32_t)(t * DDIM * 4 + d4 * 16);
                u64 q01, q23;
                // broadcast LDS.128: 4 scaled-q values (2 f32x2 pairs)
                asm("ld.shared.v2.b64 {%0, %1}, [%2];"
                    : "=l"(q01), "=l"(q23) : "r"(addr));
                u64 s0 = f32x2_add(q01, nx[2 * d4]);       // q' - x' (nx pre-negated)
                u64 s1 = f32x2_add(q23, nx[2 * d4 + 1]);
                acc[t] = f32x2_add(acc[t], f32x2_abs(s0));
                acc[t] = f32x2_add(acc[t], f32x2_abs(s1));
            }
        }

        float* op = out + (size_t)(p * BTILE) * N + n;
        #pragma unroll
        for (int t = 0; t < BTILE; ++t) {
            float lo, hi;
            asm("mov.b64 {%0, %1}, %2;" : "=f"(lo), "=f"(hi) : "l"(acc[t]));
            op[(size_t)t * N] = lo + hi;   // horizontal reduce of the d-pair lanes
        }
    }
}

extern "C" void kernel_launch(void* const* d_in, const int* in_sizes, int n_in,
                              void* d_out, int out_size) {
    const float* q  = (const float*)d_in[0];
    const float* X  = (const float*)d_in[1];
    const float* fw = (const float*)d_in[2];
    float* out = (float*)d_out;
    int N = in_sizes[1] / DDIM;                 // X is [N, 64]
    int grid = (N + BLOCK - 1) / BLOCK;         // 143 CTAs @ N=50000 -> 1 wave
    wl1_kernel<<<grid, BLOCK>>>(q, X, fw, out, N);
}